// round 2
// baseline (speedup 1.0000x reference)
#include <cuda_runtime.h>
#include <cstdint>

#define NNODES 8192
#define NEDGES 262144
#define DIN    512
#define DH     256
#define ALPHA  0.1520f
#define BETA   0.7900f

// ---------------- scratch (device globals) ---------------------------------
__device__ int   g_cnt [NNODES];
__device__ int   g_rowstart[NNODES + 1];
__device__ int   g_cursor  [NNODES];
__device__ float g_dinv[NNODES];
__device__ int   g_esrc[NEDGES];
__device__ float g_enrm[NEDGES];
__device__ float g_Y1  [NNODES * DH];   // X @ W1
__device__ float g_Y2  [NNODES * 2];    // relu(prop1+b1) @ W2
__device__ float g_ex  [NNODES];
__device__ float g_ey  [NNODES];

// ---------------- zero the small counters (every replay) -------------------
__global__ void zero_small_kernel() {
    int i = blockIdx.x * blockDim.x + threadIdx.x;
    if (i < NNODES) g_cnt[i] = 0;
}

// ---------------- degree (in-degree of dst) --------------------------------
__global__ void deg_kernel(const int* __restrict__ dst) {
    int e = blockIdx.x * blockDim.x + threadIdx.x;
    if (e < NEDGES) atomicAdd(&g_cnt[dst[e]], 1);
}

__global__ void dinv_kernel() {
    int i = blockIdx.x * blockDim.x + threadIdx.x;
    if (i < NNODES) g_dinv[i] = rsqrtf((float)g_cnt[i] + 1.0f);
}

// ---------------- exclusive scan over 8192 counts (1 block, 1024 thr) ------
__global__ __launch_bounds__(1024) void scan_kernel() {
    __shared__ int sm[1024];
    int tid = threadIdx.x;
    int base = tid * 8;
    int loc[8];
    int s = 0;
#pragma unroll
    for (int j = 0; j < 8; ++j) { loc[j] = s; s += g_cnt[base + j]; }
    sm[tid] = s;
    __syncthreads();
    // Hillis-Steele inclusive scan over 1024 chunk sums
    for (int off = 1; off < 1024; off <<= 1) {
        int v = (tid >= off) ? sm[tid - off] : 0;
        __syncthreads();
        sm[tid] += v;
        __syncthreads();
    }
    int excl = sm[tid] - s;   // exclusive prefix of this chunk
#pragma unroll
    for (int j = 0; j < 8; ++j) {
        int rs = excl + loc[j];
        g_rowstart[base + j] = rs;
        g_cursor[base + j]   = rs;
    }
    if (tid == 1023) g_rowstart[NNODES] = NEDGES;
}

// ---------------- scatter edges into CSR (by dst) --------------------------
__global__ void scatter_kernel(const int* __restrict__ src, const int* __restrict__ dst) {
    int e = blockIdx.x * blockDim.x + threadIdx.x;
    if (e >= NEDGES) return;
    int s = src[e], d = dst[e];
    int pos = atomicAdd(&g_cursor[d], 1);
    g_esrc[pos] = s;
    g_enrm[pos] = g_dinv[s] * g_dinv[d];
}

// ---------------- GEMM1: Y1[8192,256] = X[8192,512] @ W1[512,256] ----------
// BM=64 BN=64 BK=32, 256 threads, 4x4 per thread, packed fma.rn.f32x2.
#define FFMA2(d, a, b) asm("fma.rn.f32x2 %0, %1, %2, %0;" : "+l"(d) : "l"(a), "l"(b))

__global__ __launch_bounds__(256) void gemm1_kernel(const float* __restrict__ X,
                                                    const float* __restrict__ W1) {
    __shared__ float As[32][68];    // [k][m], padded
    __shared__ float Bs[32][132];   // [k][n duplicated: b0,b0,b1,b1,...], padded
    const int bm = blockIdx.y * 64;
    const int bn = blockIdx.x * 64;
    const int tid = threadIdx.x;
    const int tx = tid & 15;        // n-group (4 cols)
    const int ty = tid >> 4;        // m-group (4 rows)

    unsigned long long acc2[2][4];  // [m-pair][n], each holds (m_lo, m_hi)
#pragma unroll
    for (int a = 0; a < 2; a++)
#pragma unroll
        for (int b = 0; b < 4; b++) acc2[a][b] = 0ull;

    for (int k0 = 0; k0 < DIN; k0 += 32) {
        // A tile (64 x 32) -> As[k][m]
#pragma unroll
        for (int it = 0; it < 2; ++it) {
            int r = (tid >> 3) + it * 32;        // 0..63
            int c = (tid & 7) << 2;              // 0..28
            float4 v = *(const float4*)&X[(size_t)(bm + r) * DIN + k0 + c];
            As[c + 0][r] = v.x; As[c + 1][r] = v.y;
            As[c + 2][r] = v.z; As[c + 3][r] = v.w;
        }
        // B tile (32 x 64) -> Bs[k][dup-n] with each value duplicated
#pragma unroll
        for (int it = 0; it < 2; ++it) {
            int r = (tid >> 4) + it * 16;        // 0..31
            int c = (tid & 15) << 2;             // 0..60
            float4 w = *(const float4*)&W1[(size_t)(k0 + r) * DH + bn + c];
            float4 d0 = make_float4(w.x, w.x, w.y, w.y);
            float4 d1 = make_float4(w.z, w.z, w.w, w.w);
            *(float4*)&Bs[r][2 * c + 0] = d0;
            *(float4*)&Bs[r][2 * c + 4] = d1;
        }
        __syncthreads();
#pragma unroll
        for (int k = 0; k < 32; ++k) {
            ulonglong2 aa  = *(const ulonglong2*)&As[k][ty << 2];       // (m0,m1),(m2,m3)
            ulonglong2 b01 = *(const ulonglong2*)&Bs[k][tx << 3];       // splat n0, splat n1
            ulonglong2 b23 = *(const ulonglong2*)&Bs[k][(tx << 3) + 4]; // splat n2, splat n3
            FFMA2(acc2[0][0], aa.x, b01.x);
            FFMA2(acc2[0][1], aa.x, b01.y);
            FFMA2(acc2[0][2], aa.x, b23.x);
            FFMA2(acc2[0][3], aa.x, b23.y);
            FFMA2(acc2[1][0], aa.y, b01.x);
            FFMA2(acc2[1][1], aa.y, b01.y);
            FFMA2(acc2[1][2], aa.y, b23.x);
            FFMA2(acc2[1][3], aa.y, b23.y);
        }
        __syncthreads();
    }
#pragma unroll
    for (int mp = 0; mp < 2; ++mp) {
#pragma unroll
        for (int h = 0; h < 2; ++h) {
            float4 v;
            float2 f0 = *(float2*)&acc2[mp][0];
            float2 f1 = *(float2*)&acc2[mp][1];
            float2 f2 = *(float2*)&acc2[mp][2];
            float2 f3 = *(float2*)&acc2[mp][3];
            v.x = h ? f0.y : f0.x;
            v.y = h ? f1.y : f1.x;
            v.z = h ? f2.y : f2.x;
            v.w = h ? f3.y : f3.x;
            int row = bm + (ty << 2) + mp * 2 + h;
            *(float4*)&g_Y1[(size_t)row * DH + bn + (tx << 2)] = v;
        }
    }
}

// ---------------- fused prop1 + bias + relu + @W2 (block per node) ---------
__global__ __launch_bounds__(256) void prop1fuse_kernel(const float* __restrict__ b1,
                                                        const float* __restrict__ W2) {
    int node = blockIdx.x;
    int c = threadIdx.x;            // output column 0..255
    int e0 = g_rowstart[node];
    int e1 = g_rowstart[node + 1];
    float acc = 0.f;
    int e = e0;
    for (; e + 4 <= e1; e += 4) {
        int s0 = __ldg(&g_esrc[e + 0]);
        int s1 = __ldg(&g_esrc[e + 1]);
        int s2 = __ldg(&g_esrc[e + 2]);
        int s3 = __ldg(&g_esrc[e + 3]);
        float n0 = __ldg(&g_enrm[e + 0]);
        float n1 = __ldg(&g_enrm[e + 1]);
        float n2 = __ldg(&g_enrm[e + 2]);
        float n3 = __ldg(&g_enrm[e + 3]);
        float y0 = __ldg(&g_Y1[s0 * DH + c]);
        float y1 = __ldg(&g_Y1[s1 * DH + c]);
        float y2 = __ldg(&g_Y1[s2 * DH + c]);
        float y3 = __ldg(&g_Y1[s3 * DH + c]);
        acc = fmaf(n0, y0, acc);
        acc = fmaf(n1, y1, acc);
        acc = fmaf(n2, y2, acc);
        acc = fmaf(n3, y3, acc);
    }
    for (; e < e1; ++e) {
        int s = __ldg(&g_esrc[e]);
        float n = __ldg(&g_enrm[e]);
        acc = fmaf(n, __ldg(&g_Y1[s * DH + c]), acc);
    }
    float di = g_dinv[node];
    acc = fmaf(g_Y1[node * DH + c], di * di, acc);        // self loop
    float h = fmaxf(acc + __ldg(&b1[c]), 0.f);            // bias + relu
    float p0 = h * __ldg(&W2[2 * c + 0]);
    float p1 = h * __ldg(&W2[2 * c + 1]);
    // block reduce 256 -> 2
#pragma unroll
    for (int off = 16; off > 0; off >>= 1) {
        p0 += __shfl_down_sync(0xffffffffu, p0, off);
        p1 += __shfl_down_sync(0xffffffffu, p1, off);
    }
    __shared__ float r0[8], r1[8];
    int wid = threadIdx.x >> 5, lane = threadIdx.x & 31;
    if (lane == 0) { r0[wid] = p0; r1[wid] = p1; }
    __syncthreads();
    if (threadIdx.x == 0) {
        float a = 0.f, b = 0.f;
#pragma unroll
        for (int k = 0; k < 8; ++k) { a += r0[k]; b += r1[k]; }
        g_Y2[2 * node + 0] = a;
        g_Y2[2 * node + 1] = b;
    }
}

// ---------------- prop2 + finalize (warp per node) -------------------------
__global__ __launch_bounds__(256) void prop2fin_kernel(const float* __restrict__ b2,
                                                       float* __restrict__ out) {
    int w = (blockIdx.x * blockDim.x + threadIdx.x) >> 5;
    int lane = threadIdx.x & 31;
    if (w >= NNODES) return;
    int e0 = g_rowstart[w];
    int e1 = g_rowstart[w + 1];
    float sx = 0.f, sy = 0.f;
    for (int e = e0 + lane; e < e1; e += 32) {
        int s = __ldg(&g_esrc[e]);
        float n = __ldg(&g_enrm[e]);
        float2 y = *(const float2*)&g_Y2[2 * s];
        sx = fmaf(n, y.x, sx);
        sy = fmaf(n, y.y, sy);
    }
#pragma unroll
    for (int off = 16; off > 0; off >>= 1) {
        sx += __shfl_down_sync(0xffffffffu, sx, off);
        sy += __shfl_down_sync(0xffffffffu, sy, off);
    }
    if (lane == 0) {
        float di = g_dinv[w];
        float di2 = di * di;
        float2 y = *(const float2*)&g_Y2[2 * w];
        float ex = sx + y.x * di2 + b2[0];
        float ey = sy + y.y * di2 + b2[1];
        g_ex[w] = ex;
        g_ey[w] = ey;
        out[2 * w + 0] = ex;
        out[2 * w + 1] = ey;
    }
}

// ---------------- q[i,j] = 1/(1 + alpha * (d2)^beta) -----------------------
__device__ __forceinline__ float qval(float dx, float dy) {
    float d2 = fmaf(dx, dx, dy * dy);
    float pw = __powf(d2, BETA);
    float q  = __fdividef(1.0f, fmaf(ALPHA, pw, 1.0f));
    return d2 > 0.0f ? q : 1.0f;
}

__global__ __launch_bounds__(256) void q_kernel(float* __restrict__ qout) {
    int i = blockIdx.y * 8 + (threadIdx.x >> 5);
    int j = (blockIdx.x << 7) + ((threadIdx.x & 31) << 2);
    float xi = g_ex[i];
    float yi = g_ey[i];
    float4 xj = *(const float4*)&g_ex[j];
    float4 yj = *(const float4*)&g_ey[j];
    float4 r;
    r.x = qval(xi - xj.x, yi - yj.x);
    r.y = qval(xi - xj.y, yi - yj.y);
    r.z = qval(xi - xj.z, yi - yj.z);
    r.w = qval(xi - xj.w, yi - yj.w);
    *(float4*)&qout[(size_t)i * NNODES + j] = r;
}

// ---------------------------------------------------------------------------
extern "C" void kernel_launch(void* const* d_in, const int* in_sizes, int n_in,
                              void* d_out, int out_size) {
    const float* X  = (const float*)d_in[0];   // [8192,512]
    const int*   ei = (const int*)  d_in[1];   // [2,262144]
    const float* W1 = (const float*)d_in[2];   // [512,256]
    const float* b1 = (const float*)d_in[3];   // [256]
    const float* W2 = (const float*)d_in[4];   // [256,2]
    const float* b2 = (const float*)d_in[5];   // [2]
    float* out = (float*)d_out;                // emb (16384) then q (8192*8192)
    (void)in_sizes; (void)n_in; (void)out_size;

    const int* src = ei;
    const int* dst = ei + NEDGES;

    zero_small_kernel<<<NNODES / 256, 256>>>();
    deg_kernel<<<NEDGES / 256, 256>>>(dst);
    dinv_kernel<<<NNODES / 256, 256>>>();
    scan_kernel<<<1, 1024>>>();
    scatter_kernel<<<NEDGES / 256, 256>>>(src, dst);
    gemm1_kernel<<<dim3(DH / 64, NNODES / 64), 256>>>(X, W1);
    prop1fuse_kernel<<<NNODES, 256>>>(b1, W2);
    prop2fin_kernel<<<NNODES * 32 / 256, 256>>>(b2, out);
    q_kernel<<<dim3(NNODES / 128, NNODES / 8), 256>>>(out + NNODES * 2);
}